// round 1
// baseline (speedup 1.0000x reference)
#include <cuda_runtime.h>

// ---------------------------------------------------------------------------
// PositionAttentionModule: B=4, H=W=64, C=512, Cr=64, HW=4096
//   q = x@W1, k = x@W2 (Cr=64 each), v = x@W3 (C=512)
//   s = softmax(q @ k^T)          [B, 4096, 4096]
//   E = s @ v                     [B, 4096, 512]
//   out.flat[b, c*4096 + i] = gamma * E[b, i, c] + x.flat[b, c*4096 + i]
// All fp32. Round-0 baseline: CUDA-core SGEMM (128x128x8, 8x8 microtile,
// double-buffered smem, split-half float4 fragments -> conflict-free LDS).
// ---------------------------------------------------------------------------

constexpr int kHW  = 4096;
constexpr int kC   = 512;
constexpr int kTok = 4 * kHW;   // 16384

__device__ float g_qk [kTok * 128];                    // 8 MB   (q: cols 0-63, k: cols 64-127)
__device__ float g_v  [kTok * kC];                     // 32 MB
__device__ float g_w12[kC * 128];                      // 256 KB (W1 | W2)
__device__ float g_s  [(size_t)4 * kHW * kHW];         // 256 MB logits / softmax

// ---------------------------------------------------------------------------
__global__ __launch_bounds__(256) void concat_w(const float* __restrict__ W1,
                                                const float* __restrict__ W2) {
    int idx = blockIdx.x * 256 + threadIdx.x;          // < 65536
    int n = idx & 127;
    int k = idx >> 7;
    g_w12[idx] = (n < 64) ? W1[(k << 6) + n] : W2[(k << 6) + (n - 64)];
}

// ---------------------------------------------------------------------------
// Shared mainloop pieces (same tiling for all three GEMMs):
//   block tile 128x128, BK=8, 256 threads, thread tile 8x8 split as
//   rows {ty*4+r, 64+ty*4+r}, cols {tx*4+c, 64+tx*4+c}
// ---------------------------------------------------------------------------
#define GEMM_DECL()                                                            \
    __shared__ float As[2][8][132];                                            \
    __shared__ float Bs[2][8][132];                                            \
    const int tid = threadIdx.x;                                               \
    const int a_r = tid >> 1, a_c = (tid & 1) << 2;                            \
    const int b_r = tid >> 5, b_c = (tid & 31) << 2;                           \
    const int ty  = tid >> 4, tx  = tid & 15;                                  \
    float acc[8][8];                                                           \
    _Pragma("unroll") for (int i = 0; i < 8; i++)                              \
        _Pragma("unroll") for (int j = 0; j < 8; j++) acc[i][j] = 0.f;

#define STORE_A_TILE(buf, v)                                                   \
    As[buf][a_c + 0][a_r] = (v).x; As[buf][a_c + 1][a_r] = (v).y;              \
    As[buf][a_c + 2][a_r] = (v).z; As[buf][a_c + 3][a_r] = (v).w;

#define STORE_BT_TILE(buf, v) /* NT: B tile loaded row-major [n][k], transposed */ \
    Bs[buf][a_c + 0][a_r] = (v).x; Bs[buf][a_c + 1][a_r] = (v).y;              \
    Bs[buf][a_c + 2][a_r] = (v).z; Bs[buf][a_c + 3][a_r] = (v).w;

#define COMPUTE_KSTEPS(buf)                                                    \
    _Pragma("unroll") for (int kk = 0; kk < 8; kk++) {                         \
        float4 a0 = *(const float4*)&As[buf][kk][(ty << 2)];                   \
        float4 a1 = *(const float4*)&As[buf][kk][64 + (ty << 2)];              \
        float4 b0 = *(const float4*)&Bs[buf][kk][(tx << 2)];                   \
        float4 b1 = *(const float4*)&Bs[buf][kk][64 + (tx << 2)];              \
        float af[8]  = {a0.x, a0.y, a0.z, a0.w, a1.x, a1.y, a1.z, a1.w};       \
        float bfr[8] = {b0.x, b0.y, b0.z, b0.w, b1.x, b1.y, b1.z, b1.w};       \
        _Pragma("unroll") for (int i = 0; i < 8; i++)                          \
            _Pragma("unroll") for (int j = 0; j < 8; j++)                      \
                acc[i][j] = fmaf(af[i], bfr[j], acc[i][j]);                    \
    }

// ---------------------------------------------------------------------------
// Projections: C_out = x[16384,512] @ B[512,N]
//   mode 0: B = g_w12 (N=128, ldb=128) -> g_qk
//   mode 1: B = W3    (N=512, ldb=512) -> g_v
// ---------------------------------------------------------------------------
__global__ __launch_bounds__(256, 2) void proj_gemm(const float* __restrict__ x,
                                                    const float* __restrict__ W3,
                                                    int mode) {
    GEMM_DECL();
    const int ldb = mode ? 512 : 128;
    const int ldc = ldb;
    const float* __restrict__ B = mode ? W3 : (const float*)g_w12;
    float* __restrict__ Cp = mode ? (float*)g_v : (float*)g_qk;

    const float* Ab = x + (size_t)(blockIdx.y * 128 + a_r) * 512 + a_c;
    const float* Bb = B + (size_t)b_r * ldb + blockIdx.x * 128 + b_c;

    float4 av = *(const float4*)Ab;
    float4 bv = *(const float4*)Bb;
    STORE_A_TILE(0, av);
    *(float4*)&Bs[0][b_r][b_c] = bv;
    __syncthreads();

    int buf = 0;
    for (int k0 = 8; k0 <= 512; k0 += 8) {
        if (k0 < 512) {
            av = *(const float4*)(Ab + k0);
            bv = *(const float4*)(Bb + (size_t)k0 * ldb);
        }
        COMPUTE_KSTEPS(buf);
        if (k0 < 512) {
            buf ^= 1;
            STORE_A_TILE(buf, av);
            *(float4*)&Bs[buf][b_r][b_c] = bv;
            __syncthreads();
        }
    }

    const int row0 = blockIdx.y * 128;
    const int col0 = blockIdx.x * 128 + (tx << 2);
    #pragma unroll
    for (int i = 0; i < 8; i++) {
        int r = row0 + ((i < 4) ? (ty << 2) + i : 64 + (ty << 2) + (i - 4));
        *(float4*)(Cp + (size_t)r * ldc + col0)      = make_float4(acc[i][0], acc[i][1], acc[i][2], acc[i][3]);
        *(float4*)(Cp + (size_t)r * ldc + col0 + 64) = make_float4(acc[i][4], acc[i][5], acc[i][6], acc[i][7]);
    }
}

// ---------------------------------------------------------------------------
// Logits (NT): s[b,i,j] = sum_k q[b,i,k] * k[b,j,k], K=64
// ---------------------------------------------------------------------------
__global__ __launch_bounds__(256, 2) void logits_gemm() {
    GEMM_DECL();
    const size_t bofs = (size_t)blockIdx.z * kHW * 128;
    const float* Qb = g_qk + bofs + (size_t)(blockIdx.y * 128 + a_r) * 128 + a_c;
    const float* Kb = g_qk + bofs + (size_t)(blockIdx.x * 128 + a_r) * 128 + 64 + a_c;

    float4 av = *(const float4*)Qb;
    float4 bv = *(const float4*)Kb;
    STORE_A_TILE(0, av);
    STORE_BT_TILE(0, bv);
    __syncthreads();

    int buf = 0;
    for (int k0 = 8; k0 <= 64; k0 += 8) {
        if (k0 < 64) {
            av = *(const float4*)(Qb + k0);
            bv = *(const float4*)(Kb + k0);
        }
        COMPUTE_KSTEPS(buf);
        if (k0 < 64) {
            buf ^= 1;
            STORE_A_TILE(buf, av);
            STORE_BT_TILE(buf, bv);
            __syncthreads();
        }
    }

    float* Cp = g_s + (size_t)blockIdx.z * kHW * kHW;
    const int row0 = blockIdx.y * 128;
    const int col0 = blockIdx.x * 128 + (tx << 2);
    #pragma unroll
    for (int i = 0; i < 8; i++) {
        int r = row0 + ((i < 4) ? (ty << 2) + i : 64 + (ty << 2) + (i - 4));
        *(float4*)(Cp + (size_t)r * kHW + col0)      = make_float4(acc[i][0], acc[i][1], acc[i][2], acc[i][3]);
        *(float4*)(Cp + (size_t)r * kHW + col0 + 64) = make_float4(acc[i][4], acc[i][5], acc[i][6], acc[i][7]);
    }
}

// ---------------------------------------------------------------------------
// Row softmax over g_s (in place), one block per row, values kept in regs.
// ---------------------------------------------------------------------------
__global__ __launch_bounds__(256) void softmax_rows() {
    float* p = g_s + (size_t)blockIdx.x * kHW;
    const int tid = threadIdx.x;
    __shared__ float red[8], red2[8];

    float v[16];
    float m = -1e30f;
    #pragma unroll
    for (int k = 0; k < 16; k++) {
        v[k] = p[tid + (k << 8)];
        m = fmaxf(m, v[k]);
    }
    #pragma unroll
    for (int o = 16; o > 0; o >>= 1) m = fmaxf(m, __shfl_xor_sync(0xffffffffu, m, o));
    if ((tid & 31) == 0) red[tid >> 5] = m;
    __syncthreads();
    float bm = red[0];
    #pragma unroll
    for (int w = 1; w < 8; w++) bm = fmaxf(bm, red[w]);

    float sum = 0.f;
    #pragma unroll
    for (int k = 0; k < 16; k++) {
        v[k] = __expf(v[k] - bm);
        sum += v[k];
    }
    #pragma unroll
    for (int o = 16; o > 0; o >>= 1) sum += __shfl_xor_sync(0xffffffffu, sum, o);
    if ((tid & 31) == 0) red2[tid >> 5] = sum;
    __syncthreads();
    float bs = 0.f;
    #pragma unroll
    for (int w = 0; w < 8; w++) bs += red2[w];
    float inv = 1.f / bs;
    #pragma unroll
    for (int k = 0; k < 16; k++) p[tid + (k << 8)] = v[k] * inv;
}

// ---------------------------------------------------------------------------
// PV (NN) + fused epilogue: E = s @ v;  out[b, n*4096 + i] = gamma*E[i,n] + x[...]
// grid: x = 512/128 = 4 (channels), y = 4096/128 = 32 (queries), z = batch
// ---------------------------------------------------------------------------
__global__ __launch_bounds__(256, 2) void pv_gemm(const float* __restrict__ x,
                                                  const float* __restrict__ gamma,
                                                  float* __restrict__ out) {
    GEMM_DECL();
    const float* Ab = g_s + (size_t)blockIdx.z * kHW * kHW +
                      (size_t)(blockIdx.y * 128 + a_r) * kHW + a_c;
    const float* Bb = g_v + (size_t)blockIdx.z * kHW * kC +
                      (size_t)b_r * kC + blockIdx.x * 128 + b_c;

    float4 av = *(const float4*)Ab;
    float4 bv = *(const float4*)Bb;
    STORE_A_TILE(0, av);
    *(float4*)&Bs[0][b_r][b_c] = bv;
    __syncthreads();

    int buf = 0;
    for (int k0 = 8; k0 <= kHW; k0 += 8) {
        if (k0 < kHW) {
            av = *(const float4*)(Ab + k0);
            bv = *(const float4*)(Bb + (size_t)k0 * kC);
        }
        COMPUTE_KSTEPS(buf);
        if (k0 < kHW) {
            buf ^= 1;
            STORE_A_TILE(buf, av);
            *(float4*)&Bs[buf][b_r][b_c] = bv;
            __syncthreads();
        }
    }

    // Epilogue: out.flat[b, n*4096 + i] = gamma*acc + x.flat[b, n*4096 + i]
    // contiguous axis is i (rows) -> float4 along acc row groups.
    const float g = __ldg(gamma);
    const int i0 = blockIdx.y * 128;
    const int n0 = blockIdx.x * 128;
    const size_t bofs = (size_t)blockIdx.z * kHW * kC;
    #pragma unroll
    for (int j = 0; j < 8; j++) {
        int n = n0 + ((j < 4) ? (tx << 2) + j : 64 + (tx << 2) + (j - 4));
        size_t base = bofs + (size_t)n * kHW + i0;

        size_t a0 = base + (ty << 2);                 // rows i0 + ty*4 + 0..3
        float4 xv = *(const float4*)(x + a0);
        float4 o0 = make_float4(fmaf(g, acc[0][j], xv.x), fmaf(g, acc[1][j], xv.y),
                                fmaf(g, acc[2][j], xv.z), fmaf(g, acc[3][j], xv.w));
        *(float4*)(out + a0) = o0;

        size_t a1 = base + 64 + (ty << 2);            // rows i0 + 64 + ty*4 + 0..3
        xv = *(const float4*)(x + a1);
        float4 o1 = make_float4(fmaf(g, acc[4][j], xv.x), fmaf(g, acc[5][j], xv.y),
                                fmaf(g, acc[6][j], xv.z), fmaf(g, acc[7][j], xv.w));
        *(float4*)(out + a1) = o1;
    }
}

// ---------------------------------------------------------------------------
extern "C" void kernel_launch(void* const* d_in, const int* in_sizes, int n_in,
                              void* d_out, int out_size) {
    const float* x     = (const float*)d_in[0];
    const float* W1    = (const float*)d_in[1];
    const float* W2    = (const float*)d_in[2];
    const float* W3    = (const float*)d_in[3];
    const float* gamma = (const float*)d_in[4];
    float* out = (float*)d_out;

    concat_w<<<256, 256>>>(W1, W2);
    proj_gemm<<<dim3(1, 128), 256>>>(x, nullptr, 0);   // q|k -> g_qk
    proj_gemm<<<dim3(4, 128), 256>>>(x, W3, 1);        // v   -> g_v
    logits_gemm<<<dim3(32, 32, 4), 256>>>();           // g_s = q k^T
    softmax_rows<<<16384, 256>>>();                    // in-place softmax
    pv_gemm<<<dim3(4, 32, 4), 256>>>(x, gamma, out);   // E + fused epilogue
}

// round 5
// speedup vs baseline: 2.9366x; 2.9366x over previous
#include <cuda_runtime.h>
#include <cuda_fp16.h>
#include <cstdint>

// ---------------------------------------------------------------------------
// PositionAttentionModule: B=4, HW=4096, C=512, Cr=64
//   q|k = x@[W1|W2]      fp32 SGEMM (R1-proven)
//   v   = x@W3           fp32 SGEMM (R1-proven) -> g_v fp32
//   transpose_v          g_v -> vT fp16 [B,512,4096] (simple tiled)
//   s = q k^T            fp32 SGEMM (R1-proven)
//   softmax rows         fp32 math -> fp16 probs
//   E = s @ v            f16 HMMA (mma.sync m16n8k16), fused gamma*E + x
// R5: bisect — removed unproven vproj_mma/to_half pipeline entirely.
// ---------------------------------------------------------------------------

constexpr int kHW  = 4096;
constexpr int kC   = 512;
constexpr int kTok = 4 * kHW;   // 16384

__device__ float  g_qk [kTok * 128];                    // 8 MB (q | k)
__device__ float  g_v  [kTok * kC];                     // 32 MB fp32 v
__device__ float  g_w12[kC * 128];                      // 256 KB
__device__ float  g_s  [(size_t)4 * kHW * kHW];         // 256 MB fp32 logits
__device__ __half g_sh [(size_t)4 * kHW * kHW];         // 128 MB fp16 probs
__device__ __half g_vT [(size_t)4 * kC * kHW];          // 16 MB vT[b][n][i]

// ============================ PTX helpers ==================================
__device__ __forceinline__ uint32_t smem_u32(const void* p) {
    uint32_t a;
    asm("{ .reg .u64 t; cvta.to.shared.u64 t, %1; cvt.u32.u64 %0, t; }"
        : "=r"(a) : "l"(p));
    return a;
}
__device__ __forceinline__ void ldmx4(uint32_t& r0, uint32_t& r1, uint32_t& r2,
                                      uint32_t& r3, uint32_t a) {
    asm volatile("ldmatrix.sync.aligned.m8n8.x4.shared.b16 {%0,%1,%2,%3}, [%4];"
                 : "=r"(r0), "=r"(r1), "=r"(r2), "=r"(r3) : "r"(a));
}
__device__ __forceinline__ void mma16816(float* c, const uint32_t* a,
                                         const uint32_t* b) {
    asm volatile(
        "mma.sync.aligned.m16n8k16.row.col.f32.f16.f16.f32 "
        "{%0,%1,%2,%3}, {%4,%5,%6,%7}, {%8,%9}, {%0,%1,%2,%3};"
        : "+f"(c[0]), "+f"(c[1]), "+f"(c[2]), "+f"(c[3])
        : "r"(a[0]), "r"(a[1]), "r"(a[2]), "r"(a[3]), "r"(b[0]), "r"(b[1]));
}
#define CP16(sm, gp) \
    asm volatile("cp.async.cg.shared.global [%0], [%1], 16;" :: "r"(sm), "l"(gp))
#define CP_COMMIT() asm volatile("cp.async.commit_group;" ::: "memory")
#define CP_WAIT(n)  asm volatile("cp.async.wait_group %0;" :: "n"(n) : "memory")

// ---------------------------------------------------------------------------
__global__ __launch_bounds__(256) void concat_w(const float* __restrict__ W1,
                                                const float* __restrict__ W2) {
    int idx = blockIdx.x * 256 + threadIdx.x;
    int n = idx & 127;
    int k = idx >> 7;
    g_w12[idx] = (n < 64) ? W1[(k << 6) + n] : W2[(k << 6) + (n - 64)];
}

// ======================= fp32 SGEMM scaffolding (R1-proven) ================
#define GEMM_DECL()                                                            \
    __shared__ float As[2][8][132];                                            \
    __shared__ float Bs[2][8][132];                                            \
    const int tid = threadIdx.x;                                               \
    const int a_r = tid >> 1, a_c = (tid & 1) << 2;                            \
    const int ty  = tid >> 4, tx  = tid & 15;                                  \
    float acc[8][8];                                                           \
    _Pragma("unroll") for (int i = 0; i < 8; i++)                              \
        _Pragma("unroll") for (int j = 0; j < 8; j++) acc[i][j] = 0.f;

#define STORE_A_TILE(buf, v)                                                   \
    As[buf][a_c + 0][a_r] = (v).x; As[buf][a_c + 1][a_r] = (v).y;              \
    As[buf][a_c + 2][a_r] = (v).z; As[buf][a_c + 3][a_r] = (v).w;

#define STORE_BT_TILE(buf, v)                                                  \
    Bs[buf][a_c + 0][a_r] = (v).x; Bs[buf][a_c + 1][a_r] = (v).y;              \
    Bs[buf][a_c + 2][a_r] = (v).z; Bs[buf][a_c + 3][a_r] = (v).w;

#define COMPUTE_KSTEPS(buf)                                                    \
    _Pragma("unroll") for (int kk = 0; kk < 8; kk++) {                         \
        float4 a0 = *(const float4*)&As[buf][kk][(ty << 2)];                   \
        float4 a1 = *(const float4*)&As[buf][kk][64 + (ty << 2)];              \
        float4 b0 = *(const float4*)&Bs[buf][kk][(tx << 2)];                   \
        float4 b1 = *(const float4*)&Bs[buf][kk][64 + (tx << 2)];              \
        float af[8]  = {a0.x, a0.y, a0.z, a0.w, a1.x, a1.y, a1.z, a1.w};       \
        float bfr[8] = {b0.x, b0.y, b0.z, b0.w, b1.x, b1.y, b1.z, b1.w};       \
        _Pragma("unroll") for (int i = 0; i < 8; i++)                          \
            _Pragma("unroll") for (int j = 0; j < 8; j++)                      \
                acc[i][j] = fmaf(af[i], bfr[j], acc[i][j]);                    \
    }

// Projections (R1-proven): mode 0: qk = x @ g_w12 -> g_qk (fp32, N=128)
//                          mode 1: v  = x @ W3    -> g_v  (fp32, N=512)
__global__ __launch_bounds__(256, 2) void proj_gemm(const float* __restrict__ x,
                                                    const float* __restrict__ W3,
                                                    int mode) {
    GEMM_DECL();
    const int b_r = tid >> 5, b_c = (tid & 31) << 2;
    const int ldb = mode ? 512 : 128;
    const int ldc = ldb;
    const float* __restrict__ B = mode ? W3 : (const float*)g_w12;
    float* __restrict__ Cp = mode ? (float*)g_v : (float*)g_qk;

    const float* Ab = x + (size_t)(blockIdx.y * 128 + a_r) * 512 + a_c;
    const float* Bb = B + (size_t)b_r * ldb + blockIdx.x * 128 + b_c;

    float4 av = *(const float4*)Ab;
    float4 bv = *(const float4*)Bb;
    STORE_A_TILE(0, av);
    *(float4*)&Bs[0][b_r][b_c] = bv;
    __syncthreads();

    int buf = 0;
    for (int k0 = 8; k0 <= 512; k0 += 8) {
        if (k0 < 512) {
            av = *(const float4*)(Ab + k0);
            bv = *(const float4*)(Bb + (size_t)k0 * ldb);
        }
        COMPUTE_KSTEPS(buf);
        if (k0 < 512) {
            buf ^= 1;
            STORE_A_TILE(buf, av);
            *(float4*)&Bs[buf][b_r][b_c] = bv;
            __syncthreads();
        }
    }

    const int row0 = blockIdx.y * 128;
    const int col0 = blockIdx.x * 128 + (tx << 2);
    #pragma unroll
    for (int i = 0; i < 8; i++) {
        int r = row0 + ((i < 4) ? (ty << 2) + i : 64 + (ty << 2) + (i - 4));
        *(float4*)(Cp + (size_t)r * ldc + col0)      = make_float4(acc[i][0], acc[i][1], acc[i][2], acc[i][3]);
        *(float4*)(Cp + (size_t)r * ldc + col0 + 64) = make_float4(acc[i][4], acc[i][5], acc[i][6], acc[i][7]);
    }
}

// Transpose g_v fp32 [tok][C] -> g_vT fp16 [b][c][i]  (32x32 tiles)
__global__ __launch_bounds__(256) void transpose_v() {
    __shared__ float t[32][33];
    const int tx = threadIdx.x & 31, ty = threadIdx.x >> 5;   // 32x8
    const int c0 = blockIdx.x * 32;          // channel tile
    const int g0 = blockIdx.y * 32;          // global token tile
    #pragma unroll
    for (int j = 0; j < 4; j++) {
        int ii = ty + j * 8;
        t[ii][tx] = g_v[(size_t)(g0 + ii) * kC + c0 + tx];
    }
    __syncthreads();
    const int b  = g0 >> 12;                 // tile never straddles batch
    const int il = g0 & 4095;
    #pragma unroll
    for (int j = 0; j < 4; j++) {
        int cc = ty + j * 8;
        g_vT[((size_t)b * kC + c0 + cc) * kHW + il + tx] = __float2half_rn(t[tx][cc]);
    }
}

// Logits (NT, R1-proven): s[b,i,j] = sum_k q[b,i,k]*k[b,j,k], K=64, fp32
__global__ __launch_bounds__(256, 2) void logits_gemm() {
    GEMM_DECL();
    const size_t bofs = (size_t)blockIdx.z * kHW * 128;
    const float* Qb = g_qk + bofs + (size_t)(blockIdx.y * 128 + a_r) * 128 + a_c;
    const float* Kb = g_qk + bofs + (size_t)(blockIdx.x * 128 + a_r) * 128 + 64 + a_c;

    float4 av = *(const float4*)Qb;
    float4 bv = *(const float4*)Kb;
    STORE_A_TILE(0, av);
    STORE_BT_TILE(0, bv);
    __syncthreads();

    int buf = 0;
    for (int k0 = 8; k0 <= 64; k0 += 8) {
        if (k0 < 64) {
            av = *(const float4*)(Qb + k0);
            bv = *(const float4*)(Kb + k0);
        }
        COMPUTE_KSTEPS(buf);
        if (k0 < 64) {
            buf ^= 1;
            STORE_A_TILE(buf, av);
            STORE_BT_TILE(buf, bv);
            __syncthreads();
        }
    }

    float* Cp = g_s + (size_t)blockIdx.z * kHW * kHW;
    const int row0 = blockIdx.y * 128;
    const int col0 = blockIdx.x * 128 + (tx << 2);
    #pragma unroll
    for (int i = 0; i < 8; i++) {
        int r = row0 + ((i < 4) ? (ty << 2) + i : 64 + (ty << 2) + (i - 4));
        *(float4*)(Cp + (size_t)r * kHW + col0)      = make_float4(acc[i][0], acc[i][1], acc[i][2], acc[i][3]);
        *(float4*)(Cp + (size_t)r * kHW + col0 + 64) = make_float4(acc[i][4], acc[i][5], acc[i][6], acc[i][7]);
    }
}

// Row softmax: fp32 logits in, fp16 probs out
__global__ __launch_bounds__(256) void softmax_rows() {
    const float* p  = g_s  + (size_t)blockIdx.x * kHW;
    __half*      ph = g_sh + (size_t)blockIdx.x * kHW;
    const int tid = threadIdx.x;
    __shared__ float red[8], red2[8];

    float v[16];
    float m = -1e30f;
    #pragma unroll
    for (int k = 0; k < 16; k++) {
        v[k] = p[tid + (k << 8)];
        m = fmaxf(m, v[k]);
    }
    #pragma unroll
    for (int o = 16; o > 0; o >>= 1) m = fmaxf(m, __shfl_xor_sync(0xffffffffu, m, o));
    if ((tid & 31) == 0) red[tid >> 5] = m;
    __syncthreads();
    float bm = red[0];
    #pragma unroll
    for (int w = 1; w < 8; w++) bm = fmaxf(bm, red[w]);

    float sum = 0.f;
    #pragma unroll
    for (int k = 0; k < 16; k++) {
        v[k] = __expf(v[k] - bm);
        sum += v[k];
    }
    #pragma unroll
    for (int o = 16; o > 0; o >>= 1) sum += __shfl_xor_sync(0xffffffffu, sum, o);
    if ((tid & 31) == 0) red2[tid >> 5] = sum;
    __syncthreads();
    float bs = 0.f;
    #pragma unroll
    for (int w = 0; w < 8; w++) bs += red2[w];
    float inv = 1.f / bs;
    #pragma unroll
    for (int k = 0; k < 16; k++) ph[tid + (k << 8)] = __float2half_rn(v[k] * inv);
}

// ====================== HMMA: PV (E = s @ v), fused epilogue ===============
// CTA 128m x 128n, BK=64, 8 warps (2m x 4n), warp tile 64x32.
// A = g_sh [m][k] (ld 4096) non-trans; B = g_vT [n][k] (ld 4096) non-trans.
constexpr int PV_LDA  = 72;                         // halves, padded
constexpr int PV_ABUF = 128 * PV_LDA * 2;           // 18432 B
constexpr int PV_SMEM = 4 * PV_ABUF;                // A0 A1 B0 B1 = 73728 B

__global__ void __launch_bounds__(256, 2)
pv_mma(const float* __restrict__ x, const float* __restrict__ gamma,
       float* __restrict__ out) {
    extern __shared__ char smem[];
    const uint32_t sb  = smem_u32(smem);
    const int tid  = threadIdx.x;
    const int lane = tid & 31, wid = tid >> 5;
    const int wm = (wid & 1) * 64, wn = (wid >> 1) * 32;
    const int n0 = blockIdx.x * 128, m0 = blockIdx.y * 128, bz = blockIdx.z;

    const __half* Asrc = g_sh + (size_t)bz * kHW * kHW + (size_t)m0 * kHW;
    const __half* Bsrc = g_vT + (size_t)bz * kC * kHW + (size_t)n0 * kHW;

    const uint32_t sA[2] = {sb, sb + PV_ABUF};
    const uint32_t sB[2] = {sb + 2 * PV_ABUF, sb + 3 * PV_ABUF};

    const int ldrow  = tid >> 3;          // 0..31
    const int ldslot = (tid & 7) * 8;     // halves

    float acc[4][4][4];
    #pragma unroll
    for (int i = 0; i < 4; i++)
        #pragma unroll
        for (int j = 0; j < 4; j++)
            #pragma unroll
            for (int r = 0; r < 4; r++) acc[i][j][r] = 0.f;

    // per-lane ldmatrix base offsets (halves)
    const int aRow = wm + (lane & 15);
    const int aCol = (lane >> 4) * 8;
    const int bRow = wn + ((lane >> 4) << 3) + (lane & 7);   // n row
    const int bCol = ((lane >> 3) & 1) * 8;                  // k offset

    #pragma unroll
    for (int q = 0; q < 4; q++) {
        int r = q * 32 + ldrow;
        CP16(sA[0] + (r * PV_LDA + ldslot) * 2, Asrc + (size_t)r * kHW + ldslot);
        CP16(sB[0] + (r * PV_LDA + ldslot) * 2, Bsrc + (size_t)r * kHW + ldslot);
    }
    CP_COMMIT();

    for (int i = 0; i < 64; i++) {
        const int buf = i & 1;
        if (i < 63) {
            const int k0 = (i + 1) * 64;
            #pragma unroll
            for (int q = 0; q < 4; q++) {
                int r = q * 32 + ldrow;
                CP16(sA[buf ^ 1] + (r * PV_LDA + ldslot) * 2,
                     Asrc + (size_t)r * kHW + k0 + ldslot);
                CP16(sB[buf ^ 1] + (r * PV_LDA + ldslot) * 2,
                     Bsrc + (size_t)r * kHW + k0 + ldslot);
            }
            CP_COMMIT();
            CP_WAIT(1);
        } else {
            CP_WAIT(0);
        }
        __syncthreads();

        #pragma unroll
        for (int ks = 0; ks < 4; ks++) {
            uint32_t af[4][4], bf[4][2];
            #pragma unroll
            for (int mt = 0; mt < 4; mt++)
                ldmx4(af[mt][0], af[mt][1], af[mt][2], af[mt][3],
                      sA[buf] + ((aRow + mt * 16) * PV_LDA + aCol + ks * 16) * 2);
            #pragma unroll
            for (int np = 0; np < 2; np++)
                ldmx4(bf[np * 2][0], bf[np * 2][1], bf[np * 2 + 1][0], bf[np * 2 + 1][1],
                      sB[buf] + ((bRow + np * 16) * PV_LDA + bCol + ks * 16) * 2);
            #pragma unroll
            for (int mt = 0; mt < 4; mt++)
                #pragma unroll
                for (int nt = 0; nt < 4; nt++)
                    mma16816(acc[mt][nt], af[mt], bf[nt]);
        }
        __syncthreads();
    }

    // stage acc -> smem [n][m] fp32, then fused coalesced output
    float* stage = (float*)smem;          // [128][132]
    #pragma unroll
    for (int mt = 0; mt < 4; mt++)
        #pragma unroll
        for (int nt = 0; nt < 4; nt++)
            #pragma unroll
            for (int r = 0; r < 4; r++) {
                int m = wm + mt * 16 + (lane >> 2) + ((r >= 2) ? 8 : 0);
                int n = wn + nt * 8 + (lane & 3) * 2 + (r & 1);
                stage[n * 132 + m] = acc[mt][nt][r];
            }
    __syncthreads();

    const float g = __ldg(gamma);
    const size_t obofs = (size_t)bz * kHW * kC;
    #pragma unroll
    for (int q = 0; q < 16; q++) {
        int idx = tid + q * 256;          // 0..4095
        int n   = idx >> 5;
        int m4  = (idx & 31) << 2;
        size_t o = obofs + (size_t)(n0 + n) * kHW + m0 + m4;
        float4 xv = *(const float4*)(x + o);
        const float* sp = stage + n * 132 + m4;
        *(float4*)(out + o) = make_float4(fmaf(g, sp[0], xv.x), fmaf(g, sp[1], xv.y),
                                          fmaf(g, sp[2], xv.z), fmaf(g, sp[3], xv.w));
    }
}

// ---------------------------------------------------------------------------
extern "C" void kernel_launch(void* const* d_in, const int* in_sizes, int n_in,
                              void* d_out, int out_size) {
    const float* x     = (const float*)d_in[0];
    const float* W1    = (const float*)d_in[1];
    const float* W2    = (const float*)d_in[2];
    const float* W3    = (const float*)d_in[3];
    const float* gamma = (const float*)d_in[4];
    float* out = (float*)d_out;

    cudaFuncSetAttribute(pv_mma, cudaFuncAttributeMaxDynamicSharedMemorySize, PV_SMEM);

    concat_w<<<256, 256>>>(W1, W2);
    proj_gemm<<<dim3(1, 128), 256>>>(x, nullptr, 0);    // q|k fp32 (proven)
    proj_gemm<<<dim3(4, 128), 256>>>(x, W3, 1);         // v fp32   (proven)
    transpose_v<<<dim3(16, 512), 256>>>();              // vT fp16
    logits_gemm<<<dim3(32, 32, 4), 256>>>();            // fp32 logits (proven)
    softmax_rows<<<16384, 256>>>();                     // fp16 probs
    pv_mma<<<dim3(4, 32, 4), 256, PV_SMEM>>>(x, gamma, out);
}

// round 7
// speedup vs baseline: 3.8190x; 1.3005x over previous
#include <cuda_runtime.h>
#include <cuda_fp16.h>
#include <cstdint>

// ---------------------------------------------------------------------------
// PositionAttentionModule: B=4, HW=4096, C=512, Cr=64
//   q|k = x@[W1|W2]      fp32 SGEMM (proven)
//   v   = x@W3           f16 HMMA NT (pv_mma clone) -> vT fp16 [B,512,4096]
//   s = q k^T            fp32 SGEMM (proven)
//   softmax rows         fp32 math -> fp16 probs (proven)
//   E = s @ v            f16 HMMA NT (proven), fused gamma*E + x
// R7 fix: NEVER pass __device__ globals as kernel args from host (host shadow
//   address + ATS made writes land in host memory silently -> g_xh stayed 0).
//   All device globals are now referenced inside kernel bodies only.
// ---------------------------------------------------------------------------

constexpr int kHW  = 4096;
constexpr int kC   = 512;
constexpr int kTok = 4 * kHW;   // 16384

__device__ float  g_qk  [kTok * 128];                   // 8 MB (q | k)
__device__ float  g_w12 [kC * 128];                     // 256 KB
__device__ float  g_s   [(size_t)4 * kHW * kHW];        // 256 MB fp32 logits
__device__ __half g_sh  [(size_t)4 * kHW * kHW];        // 128 MB fp16 probs
__device__ __half g_vT  [(size_t)4 * kC * kHW];         // 16 MB vT[b][n][i]
__device__ __half g_xh  [(size_t)kTok * kC];            // 16 MB x fp16 [m][k]
__device__ __half g_w3T [kC * kC];                      // 512 KB W3^T fp16 [n][k]

// ============================ PTX helpers ==================================
__device__ __forceinline__ uint32_t smem_u32(const void* p) {
    uint32_t a;
    asm("{ .reg .u64 t; cvta.to.shared.u64 t, %1; cvt.u32.u64 %0, t; }"
        : "=r"(a) : "l"(p));
    return a;
}
__device__ __forceinline__ void ldmx4(uint32_t& r0, uint32_t& r1, uint32_t& r2,
                                      uint32_t& r3, uint32_t a) {
    asm volatile("ldmatrix.sync.aligned.m8n8.x4.shared.b16 {%0,%1,%2,%3}, [%4];"
                 : "=r"(r0), "=r"(r1), "=r"(r2), "=r"(r3) : "r"(a));
}
__device__ __forceinline__ void mma16816(float* c, const uint32_t* a,
                                         const uint32_t* b) {
    asm volatile(
        "mma.sync.aligned.m16n8k16.row.col.f32.f16.f16.f32 "
        "{%0,%1,%2,%3}, {%4,%5,%6,%7}, {%8,%9}, {%0,%1,%2,%3};"
        : "+f"(c[0]), "+f"(c[1]), "+f"(c[2]), "+f"(c[3])
        : "r"(a[0]), "r"(a[1]), "r"(a[2]), "r"(a[3]), "r"(b[0]), "r"(b[1]));
}
#define CP16(sm, gp) \
    asm volatile("cp.async.cg.shared.global [%0], [%1], 16;" :: "r"(sm), "l"(gp))
#define CP_COMMIT() asm volatile("cp.async.commit_group;" ::: "memory")
#define CP_WAIT(n)  asm volatile("cp.async.wait_group %0;" :: "n"(n) : "memory")

// ---------------------------------------------------------------------------
__global__ __launch_bounds__(256) void concat_w(const float* __restrict__ W1,
                                                const float* __restrict__ W2) {
    int idx = blockIdx.x * 256 + threadIdx.x;
    int n = idx & 127;
    int k = idx >> 7;
    g_w12[idx] = (n < 64) ? W1[(k << 6) + n] : W2[(k << 6) + (n - 64)];
}

// x fp32 -> g_xh fp16 (device global referenced IN KERNEL, not via host arg)
__global__ __launch_bounds__(256) void to_half_x(const float* __restrict__ x) {
    int idx = blockIdx.x * 256 + threadIdx.x;           // < 2097152
    float4 v = *(const float4*)(x + (size_t)idx * 4);
    __half2* d = (__half2*)(g_xh + (size_t)idx * 4);
    d[0] = __floats2half2_rn(v.x, v.y);
    d[1] = __floats2half2_rn(v.z, v.w);
}

// W3 [k][n] fp32 -> g_w3T fp16 [n][k]  (32x32 tiles)
__global__ __launch_bounds__(256) void transpose_w3(const float* __restrict__ W3) {
    __shared__ float t[32][33];
    const int tx = threadIdx.x & 31, ty = threadIdx.x >> 5;   // 32x8
    const int n0 = blockIdx.x * 32;
    const int k0 = blockIdx.y * 32;
    #pragma unroll
    for (int j = 0; j < 4; j++) {
        int kk = ty + j * 8;
        t[kk][tx] = W3[(size_t)(k0 + kk) * kC + n0 + tx];
    }
    __syncthreads();
    #pragma unroll
    for (int j = 0; j < 4; j++) {
        int nn = ty + j * 8;
        g_w3T[(size_t)(n0 + nn) * kC + k0 + tx] = __float2half_rn(t[tx][nn]);
    }
}

// ======================= fp32 SGEMM scaffolding (proven) ===================
#define GEMM_DECL()                                                            \
    __shared__ float As[2][8][132];                                            \
    __shared__ float Bs[2][8][132];                                            \
    const int tid = threadIdx.x;                                               \
    const int a_r = tid >> 1, a_c = (tid & 1) << 2;                            \
    const int ty  = tid >> 4, tx  = tid & 15;                                  \
    float acc[8][8];                                                           \
    _Pragma("unroll") for (int i = 0; i < 8; i++)                              \
        _Pragma("unroll") for (int j = 0; j < 8; j++) acc[i][j] = 0.f;

#define STORE_A_TILE(buf, v)                                                   \
    As[buf][a_c + 0][a_r] = (v).x; As[buf][a_c + 1][a_r] = (v).y;              \
    As[buf][a_c + 2][a_r] = (v).z; As[buf][a_c + 3][a_r] = (v).w;

#define STORE_BT_TILE(buf, v)                                                  \
    Bs[buf][a_c + 0][a_r] = (v).x; Bs[buf][a_c + 1][a_r] = (v).y;              \
    Bs[buf][a_c + 2][a_r] = (v).z; Bs[buf][a_c + 3][a_r] = (v).w;

#define COMPUTE_KSTEPS(buf)                                                    \
    _Pragma("unroll") for (int kk = 0; kk < 8; kk++) {                         \
        float4 a0 = *(const float4*)&As[buf][kk][(ty << 2)];                   \
        float4 a1 = *(const float4*)&As[buf][kk][64 + (ty << 2)];              \
        float4 b0 = *(const float4*)&Bs[buf][kk][(tx << 2)];                   \
        float4 b1 = *(const float4*)&Bs[buf][kk][64 + (tx << 2)];              \
        float af[8]  = {a0.x, a0.y, a0.z, a0.w, a1.x, a1.y, a1.z, a1.w};       \
        float bfr[8] = {b0.x, b0.y, b0.z, b0.w, b1.x, b1.y, b1.z, b1.w};       \
        _Pragma("unroll") for (int i = 0; i < 8; i++)                          \
            _Pragma("unroll") for (int j = 0; j < 8; j++)                      \
                acc[i][j] = fmaf(af[i], bfr[j], acc[i][j]);                    \
    }

// q|k projection (proven): g_qk = x @ g_w12, fp32
__global__ __launch_bounds__(256, 2) void proj_gemm(const float* __restrict__ x) {
    GEMM_DECL();
    const int b_r = tid >> 5, b_c = (tid & 31) << 2;
    const float* Ab = x + (size_t)(blockIdx.y * 128 + a_r) * 512 + a_c;
    const float* Bb = (const float*)g_w12 + (size_t)b_r * 128 + b_c;

    float4 av = *(const float4*)Ab;
    float4 bv = *(const float4*)Bb;
    STORE_A_TILE(0, av);
    *(float4*)&Bs[0][b_r][b_c] = bv;
    __syncthreads();

    int buf = 0;
    for (int k0 = 8; k0 <= 512; k0 += 8) {
        if (k0 < 512) {
            av = *(const float4*)(Ab + k0);
            bv = *(const float4*)(Bb + (size_t)k0 * 128);
        }
        COMPUTE_KSTEPS(buf);
        if (k0 < 512) {
            buf ^= 1;
            STORE_A_TILE(buf, av);
            *(float4*)&Bs[buf][b_r][b_c] = bv;
            __syncthreads();
        }
    }

    const int row0 = blockIdx.y * 128;
    const int c0 = (tx << 2);
    #pragma unroll
    for (int i = 0; i < 8; i++) {
        int r = row0 + ((i < 4) ? (ty << 2) + i : 64 + (ty << 2) + (i - 4));
        *(float4*)(g_qk + (size_t)r * 128 + c0)      = make_float4(acc[i][0], acc[i][1], acc[i][2], acc[i][3]);
        *(float4*)(g_qk + (size_t)r * 128 + c0 + 64) = make_float4(acc[i][4], acc[i][5], acc[i][6], acc[i][7]);
    }
}

// Logits (NT, proven): s[b,i,j] = sum_k q[b,i,k]*k[b,j,k], K=64, fp32
__global__ __launch_bounds__(256, 2) void logits_gemm() {
    GEMM_DECL();
    const size_t bofs = (size_t)blockIdx.z * kHW * 128;
    const float* Qb = g_qk + bofs + (size_t)(blockIdx.y * 128 + a_r) * 128 + a_c;
    const float* Kb = g_qk + bofs + (size_t)(blockIdx.x * 128 + a_r) * 128 + 64 + a_c;

    float4 av = *(const float4*)Qb;
    float4 bv = *(const float4*)Kb;
    STORE_A_TILE(0, av);
    STORE_BT_TILE(0, bv);
    __syncthreads();

    int buf = 0;
    for (int k0 = 8; k0 <= 64; k0 += 8) {
        if (k0 < 64) {
            av = *(const float4*)(Qb + k0);
            bv = *(const float4*)(Kb + k0);
        }
        COMPUTE_KSTEPS(buf);
        if (k0 < 64) {
            buf ^= 1;
            STORE_A_TILE(buf, av);
            STORE_BT_TILE(buf, bv);
            __syncthreads();
        }
    }

    float* Cp = g_s + (size_t)blockIdx.z * kHW * kHW;
    const int row0 = blockIdx.y * 128;
    const int col0 = blockIdx.x * 128 + (tx << 2);
    #pragma unroll
    for (int i = 0; i < 8; i++) {
        int r = row0 + ((i < 4) ? (ty << 2) + i : 64 + (ty << 2) + (i - 4));
        *(float4*)(Cp + (size_t)r * kHW + col0)      = make_float4(acc[i][0], acc[i][1], acc[i][2], acc[i][3]);
        *(float4*)(Cp + (size_t)r * kHW + col0 + 64) = make_float4(acc[i][4], acc[i][5], acc[i][6], acc[i][7]);
    }
}

// Row softmax (proven): fp32 logits in, fp16 probs out
__global__ __launch_bounds__(256) void softmax_rows() {
    const float* p  = g_s  + (size_t)blockIdx.x * kHW;
    __half*      ph = g_sh + (size_t)blockIdx.x * kHW;
    const int tid = threadIdx.x;
    __shared__ float red[8], red2[8];

    float v[16];
    float m = -1e30f;
    #pragma unroll
    for (int k = 0; k < 16; k++) {
        v[k] = p[tid + (k << 8)];
        m = fmaxf(m, v[k]);
    }
    #pragma unroll
    for (int o = 16; o > 0; o >>= 1) m = fmaxf(m, __shfl_xor_sync(0xffffffffu, m, o));
    if ((tid & 31) == 0) red[tid >> 5] = m;
    __syncthreads();
    float bm = red[0];
    #pragma unroll
    for (int w = 1; w < 8; w++) bm = fmaxf(bm, red[w]);

    float sum = 0.f;
    #pragma unroll
    for (int k = 0; k < 16; k++) {
        v[k] = __expf(v[k] - bm);
        sum += v[k];
    }
    #pragma unroll
    for (int o = 16; o > 0; o >>= 1) sum += __shfl_xor_sync(0xffffffffu, sum, o);
    if ((tid & 31) == 0) red2[tid >> 5] = sum;
    __syncthreads();
    float bs = 0.f;
    #pragma unroll
    for (int w = 0; w < 8; w++) bs += red2[w];
    float inv = 1.f / bs;
    #pragma unroll
    for (int k = 0; k < 16; k++) ph[tid + (k << 8)] = __float2half_rn(v[k] * inv);
}

// ============ HMMA NT skeleton constants (shared by pv & vproj) ============
constexpr int PV_LDA  = 72;                         // halves, padded
constexpr int PV_ABUF = 128 * PV_LDA * 2;           // 18432 B
constexpr int PV_SMEM = 4 * PV_ABUF;                // 73728 B

// ====================== HMMA: PV (E = s @ v), fused epilogue (proven) ======
__global__ void __launch_bounds__(256, 2)
pv_mma(const float* __restrict__ x, const float* __restrict__ gamma,
       float* __restrict__ out) {
    extern __shared__ char smem[];
    const uint32_t sb  = smem_u32(smem);
    const int tid  = threadIdx.x;
    const int lane = tid & 31, wid = tid >> 5;
    const int wm = (wid & 1) * 64, wn = (wid >> 1) * 32;
    const int n0 = blockIdx.x * 128, m0 = blockIdx.y * 128, bz = blockIdx.z;

    const __half* Asrc = g_sh + (size_t)bz * kHW * kHW + (size_t)m0 * kHW;
    const __half* Bsrc = g_vT + (size_t)bz * kC * kHW + (size_t)n0 * kHW;

    const uint32_t sA[2] = {sb, sb + PV_ABUF};
    const uint32_t sB[2] = {sb + 2 * PV_ABUF, sb + 3 * PV_ABUF};

    const int ldrow  = tid >> 3;
    const int ldslot = (tid & 7) * 8;

    float acc[4][4][4];
    #pragma unroll
    for (int i = 0; i < 4; i++)
        #pragma unroll
        for (int j = 0; j < 4; j++)
            #pragma unroll
            for (int r = 0; r < 4; r++) acc[i][j][r] = 0.f;

    const int aRow = wm + (lane & 15);
    const int aCol = (lane >> 4) * 8;
    const int bRow = wn + ((lane >> 4) << 3) + (lane & 7);
    const int bCol = ((lane >> 3) & 1) * 8;

    #pragma unroll
    for (int q = 0; q < 4; q++) {
        int r = q * 32 + ldrow;
        CP16(sA[0] + (r * PV_LDA + ldslot) * 2, Asrc + (size_t)r * kHW + ldslot);
        CP16(sB[0] + (r * PV_LDA + ldslot) * 2, Bsrc + (size_t)r * kHW + ldslot);
    }
    CP_COMMIT();

    for (int i = 0; i < 64; i++) {
        const int buf = i & 1;
        if (i < 63) {
            const int k0 = (i + 1) * 64;
            #pragma unroll
            for (int q = 0; q < 4; q++) {
                int r = q * 32 + ldrow;
                CP16(sA[buf ^ 1] + (r * PV_LDA + ldslot) * 2,
                     Asrc + (size_t)r * kHW + k0 + ldslot);
                CP16(sB[buf ^ 1] + (r * PV_LDA + ldslot) * 2,
                     Bsrc + (size_t)r * kHW + k0 + ldslot);
            }
            CP_COMMIT();
            CP_WAIT(1);
        } else {
            CP_WAIT(0);
        }
        __syncthreads();

        #pragma unroll
        for (int ks = 0; ks < 4; ks++) {
            uint32_t af[4][4], bf[4][2];
            #pragma unroll
            for (int mt = 0; mt < 4; mt++)
                ldmx4(af[mt][0], af[mt][1], af[mt][2], af[mt][3],
                      sA[buf] + ((aRow + mt * 16) * PV_LDA + aCol + ks * 16) * 2);
            #pragma unroll
            for (int np = 0; np < 2; np++)
                ldmx4(bf[np * 2][0], bf[np * 2][1], bf[np * 2 + 1][0], bf[np * 2 + 1][1],
                      sB[buf] + ((bRow + np * 16) * PV_LDA + bCol + ks * 16) * 2);
            #pragma unroll
            for (int mt = 0; mt < 4; mt++)
                #pragma unroll
                for (int nt = 0; nt < 4; nt++)
                    mma16816(acc[mt][nt], af[mt], bf[nt]);
        }
        __syncthreads();
    }

    float* stage = (float*)smem;          // [128][132]
    #pragma unroll
    for (int mt = 0; mt < 4; mt++)
        #pragma unroll
        for (int nt = 0; nt < 4; nt++)
            #pragma unroll
            for (int r = 0; r < 4; r++) {
                int m = wm + mt * 16 + (lane >> 2) + ((r >= 2) ? 8 : 0);
                int n = wn + nt * 8 + (lane & 3) * 2 + (r & 1);
                stage[n * 132 + m] = acc[mt][nt][r];
            }
    __syncthreads();

    const float g = __ldg(gamma);
    const size_t obofs = (size_t)bz * kHW * kC;
    #pragma unroll
    for (int q = 0; q < 16; q++) {
        int idx = tid + q * 256;
        int n   = idx >> 5;
        int m4  = (idx & 31) << 2;
        size_t o = obofs + (size_t)(n0 + n) * kHW + m0 + m4;
        float4 xv = *(const float4*)(x + o);
        const float* sp = stage + n * 132 + m4;
        *(float4*)(out + o) = make_float4(fmaf(g, sp[0], xv.x), fmaf(g, sp[1], xv.y),
                                          fmaf(g, sp[2], xv.z), fmaf(g, sp[3], xv.w));
    }
}

// ============ HMMA: V-proj NT clone of pv_mma (vT = (x @ W3)^T) ============
// A = g_xh [m][k] ld 512; B = g_w3T [n][k] ld 512. K=512 -> 8 chunks.
__global__ void __launch_bounds__(256, 2) vproj_mma() {
    extern __shared__ char smem[];
    const uint32_t sb  = smem_u32(smem);
    const int tid  = threadIdx.x;
    const int lane = tid & 31, wid = tid >> 5;
    const int wm = (wid & 1) * 64, wn = (wid >> 1) * 32;
    const int n0 = blockIdx.x * 128, m0 = blockIdx.y * 128;

    const __half* Asrc = g_xh + (size_t)m0 * kC;
    const __half* Bsrc = g_w3T + (size_t)n0 * kC;

    const uint32_t sA[2] = {sb, sb + PV_ABUF};
    const uint32_t sB[2] = {sb + 2 * PV_ABUF, sb + 3 * PV_ABUF};

    const int ldrow  = tid >> 3;
    const int ldslot = (tid & 7) * 8;

    float acc[4][4][4];
    #pragma unroll
    for (int i = 0; i < 4; i++)
        #pragma unroll
        for (int j = 0; j < 4; j++)
            #pragma unroll
            for (int r = 0; r < 4; r++) acc[i][j][r] = 0.f;

    const int aRow = wm + (lane & 15);
    const int aCol = (lane >> 4) * 8;
    const int bRow = wn + ((lane >> 4) << 3) + (lane & 7);
    const int bCol = ((lane >> 3) & 1) * 8;

    #pragma unroll
    for (int q = 0; q < 4; q++) {
        int r = q * 32 + ldrow;
        CP16(sA[0] + (r * PV_LDA + ldslot) * 2, Asrc + (size_t)r * kC + ldslot);
        CP16(sB[0] + (r * PV_LDA + ldslot) * 2, Bsrc + (size_t)r * kC + ldslot);
    }
    CP_COMMIT();

    for (int i = 0; i < 8; i++) {
        const int buf = i & 1;
        if (i < 7) {
            const int k0 = (i + 1) * 64;
            #pragma unroll
            for (int q = 0; q < 4; q++) {
                int r = q * 32 + ldrow;
                CP16(sA[buf ^ 1] + (r * PV_LDA + ldslot) * 2,
                     Asrc + (size_t)r * kC + k0 + ldslot);
                CP16(sB[buf ^ 1] + (r * PV_LDA + ldslot) * 2,
                     Bsrc + (size_t)r * kC + k0 + ldslot);
            }
            CP_COMMIT();
            CP_WAIT(1);
        } else {
            CP_WAIT(0);
        }
        __syncthreads();

        #pragma unroll
        for (int ks = 0; ks < 4; ks++) {
            uint32_t af[4][4], bf[4][2];
            #pragma unroll
            for (int mt = 0; mt < 4; mt++)
                ldmx4(af[mt][0], af[mt][1], af[mt][2], af[mt][3],
                      sA[buf] + ((aRow + mt * 16) * PV_LDA + aCol + ks * 16) * 2);
            #pragma unroll
            for (int np = 0; np < 2; np++)
                ldmx4(bf[np * 2][0], bf[np * 2][1], bf[np * 2 + 1][0], bf[np * 2 + 1][1],
                      sB[buf] + ((bRow + np * 16) * PV_LDA + bCol + ks * 16) * 2);
            #pragma unroll
            for (int mt = 0; mt < 4; mt++)
                #pragma unroll
                for (int nt = 0; nt < 4; nt++)
                    mma16816(acc[mt][nt], af[mt], bf[nt]);
        }
        __syncthreads();
    }

    // stage [n][m] fp16 -> coalesced vT stores
    __half* stage = (__half*)smem;        // [128][136]
    constexpr int SLD = 136;
    #pragma unroll
    for (int mt = 0; mt < 4; mt++)
        #pragma unroll
        for (int nt = 0; nt < 4; nt++)
            #pragma unroll
            for (int r = 0; r < 4; r++) {
                int m = wm + mt * 16 + (lane >> 2) + ((r >= 2) ? 8 : 0);
                int n = wn + nt * 8 + (lane & 3) * 2 + (r & 1);
                stage[n * SLD + m] = __float2half_rn(acc[mt][nt][r]);
            }
    __syncthreads();

    const int bz = m0 >> 12;              // 128-row tile never straddles batch
    const int ml = m0 & 4095;
    #pragma unroll
    for (int q = 0; q < 8; q++) {
        int idx = tid + q * 256;          // 0..2047
        int n   = idx >> 4;
        int m8  = (idx & 15) << 3;
        __half* dst = g_vT + ((size_t)bz * kC + n0 + n) * kHW + ml + m8;
        *(uint4*)dst = *(uint4*)(stage + n * SLD + m8);
    }
}

// ---------------------------------------------------------------------------
extern "C" void kernel_launch(void* const* d_in, const int* in_sizes, int n_in,
                              void* d_out, int out_size) {
    const float* x     = (const float*)d_in[0];
    const float* W1    = (const float*)d_in[1];
    const float* W2    = (const float*)d_in[2];
    const float* W3    = (const float*)d_in[3];
    const float* gamma = (const float*)d_in[4];
    float* out = (float*)d_out;

    cudaFuncSetAttribute(pv_mma, cudaFuncAttributeMaxDynamicSharedMemorySize, PV_SMEM);
    cudaFuncSetAttribute(vproj_mma, cudaFuncAttributeMaxDynamicSharedMemorySize, PV_SMEM);

    concat_w<<<256, 256>>>(W1, W2);
    to_half_x<<<8192, 256>>>(x);                         // x fp16 [m][k] (in-kernel global)
    transpose_w3<<<dim3(16, 16), 256>>>(W3);             // W3^T fp16 [n][k]
    proj_gemm<<<dim3(1, 128), 256>>>(x);                 // q|k fp32 (proven)
    vproj_mma<<<dim3(4, 128), 256, PV_SMEM>>>();         // vT fp16 (HMMA NT clone)
    logits_gemm<<<dim3(32, 32, 4), 256>>>();             // fp32 logits (proven)
    softmax_rows<<<16384, 256>>>();                      // fp16 probs (proven)
    pv_mma<<<dim3(4, 32, 4), 256, PV_SMEM>>>(x, gamma, out);
}

// round 8
// speedup vs baseline: 4.3419x; 1.1369x over previous
#include <cuda_runtime.h>
#include <cuda_fp16.h>
#include <cstdint>

// ---------------------------------------------------------------------------
// PositionAttentionModule: B=4, HW=4096, C=512, Cr=64
//   q|k = x@[W1|W2]      fp32 SGEMM (proven)
//   split q,k            fp32 -> (hi,lo) fp16 pairs (exact to 2^-22)
//   v   = x@W3           f16 HMMA NT (proven) -> vT fp16
//   s = q k^T            f16 HMMA NT, 3-term split (hi*hi + lo*hi + hi*lo)
//   softmax rows         fp32 math, vectorized -> fp16 probs
//   E = s @ v            f16 HMMA NT (proven), fused gamma*E + x
// Rule learned R7: device globals referenced ONLY inside kernel bodies.
// ---------------------------------------------------------------------------

constexpr int kHW  = 4096;
constexpr int kC   = 512;
constexpr int kTok = 4 * kHW;   // 16384

__device__ float  g_qk  [kTok * 128];                   // 8 MB (q | k) fp32
__device__ __half g_qs  [kTok * 128];                   // 4 MB q split [hi|lo]
__device__ __half g_ks  [kTok * 128];                   // 4 MB k split [hi|lo]
__device__ float  g_w12 [kC * 128];                     // 256 KB
__device__ float  g_s   [(size_t)4 * kHW * kHW];        // 256 MB fp32 logits
__device__ __half g_sh  [(size_t)4 * kHW * kHW];        // 128 MB fp16 probs
__device__ __half g_vT  [(size_t)4 * kC * kHW];         // 16 MB vT[b][n][i]
__device__ __half g_xh  [(size_t)kTok * kC];            // 16 MB x fp16 [m][k]
__device__ __half g_w3T [kC * kC];                      // 512 KB W3^T fp16 [n][k]

// ============================ PTX helpers ==================================
__device__ __forceinline__ uint32_t smem_u32(const void* p) {
    uint32_t a;
    asm("{ .reg .u64 t; cvta.to.shared.u64 t, %1; cvt.u32.u64 %0, t; }"
        : "=r"(a) : "l"(p));
    return a;
}
__device__ __forceinline__ void ldmx4(uint32_t& r0, uint32_t& r1, uint32_t& r2,
                                      uint32_t& r3, uint32_t a) {
    asm volatile("ldmatrix.sync.aligned.m8n8.x4.shared.b16 {%0,%1,%2,%3}, [%4];"
                 : "=r"(r0), "=r"(r1), "=r"(r2), "=r"(r3) : "r"(a));
}
__device__ __forceinline__ void mma16816(float* c, const uint32_t* a,
                                         const uint32_t* b) {
    asm volatile(
        "mma.sync.aligned.m16n8k16.row.col.f32.f16.f16.f32 "
        "{%0,%1,%2,%3}, {%4,%5,%6,%7}, {%8,%9}, {%0,%1,%2,%3};"
        : "+f"(c[0]), "+f"(c[1]), "+f"(c[2]), "+f"(c[3])
        : "r"(a[0]), "r"(a[1]), "r"(a[2]), "r"(a[3]), "r"(b[0]), "r"(b[1]));
}
#define CP16(sm, gp) \
    asm volatile("cp.async.cg.shared.global [%0], [%1], 16;" :: "r"(sm), "l"(gp))
#define CP_COMMIT() asm volatile("cp.async.commit_group;" ::: "memory")
#define CP_WAIT(n)  asm volatile("cp.async.wait_group %0;" :: "n"(n) : "memory")

// ---------------------------------------------------------------------------
__global__ __launch_bounds__(256) void concat_w(const float* __restrict__ W1,
                                                const float* __restrict__ W2) {
    int idx = blockIdx.x * 256 + threadIdx.x;
    int n = idx & 127;
    int k = idx >> 7;
    g_w12[idx] = (n < 64) ? W1[(k << 6) + n] : W2[(k << 6) + (n - 64)];
}

__global__ __launch_bounds__(256) void to_half_x(const float* __restrict__ x) {
    int idx = blockIdx.x * 256 + threadIdx.x;
    float4 v = *(const float4*)(x + (size_t)idx * 4);
    __half2* d = (__half2*)(g_xh + (size_t)idx * 4);
    d[0] = __floats2half2_rn(v.x, v.y);
    d[1] = __floats2half2_rn(v.z, v.w);
}

__global__ __launch_bounds__(256) void transpose_w3(const float* __restrict__ W3) {
    __shared__ float t[32][33];
    const int tx = threadIdx.x & 31, ty = threadIdx.x >> 5;
    const int n0 = blockIdx.x * 32;
    const int k0 = blockIdx.y * 32;
    #pragma unroll
    for (int j = 0; j < 4; j++) {
        int kk = ty + j * 8;
        t[kk][tx] = W3[(size_t)(k0 + kk) * kC + n0 + tx];
    }
    __syncthreads();
    #pragma unroll
    for (int j = 0; j < 4; j++) {
        int nn = ty + j * 8;
        g_w3T[(size_t)(n0 + nn) * kC + k0 + tx] = __float2half_rn(t[tx][nn]);
    }
}

// q|k fp32 -> (hi, lo) fp16 split.  q cols 0-63 of g_qk, k cols 64-127.
__global__ __launch_bounds__(256) void split_qk() {
    int idx = blockIdx.x * 256 + threadIdx.x;           // < 2097152
    int t = idx >> 7, c = idx & 127;
    float v = g_qk[idx];
    __half hi = __float2half_rn(v);
    __half lo = __float2half_rn(v - __half2float(hi));
    if (c < 64) {
        g_qs[t * 128 + c]      = hi;
        g_qs[t * 128 + 64 + c] = lo;
    } else {
        g_ks[t * 128 + c - 64] = hi;
        g_ks[t * 128 + c]      = lo;
    }
}

// ======================= fp32 SGEMM scaffolding (proven) ===================
#define GEMM_DECL()                                                            \
    __shared__ float As[2][8][132];                                            \
    __shared__ float Bs[2][8][132];                                            \
    const int tid = threadIdx.x;                                               \
    const int a_r = tid >> 1, a_c = (tid & 1) << 2;                            \
    const int ty  = tid >> 4, tx  = tid & 15;                                  \
    float acc[8][8];                                                           \
    _Pragma("unroll") for (int i = 0; i < 8; i++)                              \
        _Pragma("unroll") for (int j = 0; j < 8; j++) acc[i][j] = 0.f;

#define STORE_A_TILE(buf, v)                                                   \
    As[buf][a_c + 0][a_r] = (v).x; As[buf][a_c + 1][a_r] = (v).y;              \
    As[buf][a_c + 2][a_r] = (v).z; As[buf][a_c + 3][a_r] = (v).w;

#define COMPUTE_KSTEPS(buf)                                                    \
    _Pragma("unroll") for (int kk = 0; kk < 8; kk++) {                         \
        float4 a0 = *(const float4*)&As[buf][kk][(ty << 2)];                   \
        float4 a1 = *(const float4*)&As[buf][kk][64 + (ty << 2)];              \
        float4 b0 = *(const float4*)&Bs[buf][kk][(tx << 2)];                   \
        float4 b1 = *(const float4*)&Bs[buf][kk][64 + (tx << 2)];              \
        float af[8]  = {a0.x, a0.y, a0.z, a0.w, a1.x, a1.y, a1.z, a1.w};       \
        float bfr[8] = {b0.x, b0.y, b0.z, b0.w, b1.x, b1.y, b1.z, b1.w};       \
        _Pragma("unroll") for (int i = 0; i < 8; i++)                          \
            _Pragma("unroll") for (int j = 0; j < 8; j++)                      \
                acc[i][j] = fmaf(af[i], bfr[j], acc[i][j]);                    \
    }

// q|k projection (proven): g_qk = x @ g_w12, fp32
__global__ __launch_bounds__(256, 2) void proj_gemm(const float* __restrict__ x) {
    GEMM_DECL();
    const int b_r = tid >> 5, b_c = (tid & 31) << 2;
    const float* Ab = x + (size_t)(blockIdx.y * 128 + a_r) * 512 + a_c;
    const float* Bb = (const float*)g_w12 + (size_t)b_r * 128 + b_c;

    float4 av = *(const float4*)Ab;
    float4 bv = *(const float4*)Bb;
    STORE_A_TILE(0, av);
    *(float4*)&Bs[0][b_r][b_c] = bv;
    __syncthreads();

    int buf = 0;
    for (int k0 = 8; k0 <= 512; k0 += 8) {
        if (k0 < 512) {
            av = *(const float4*)(Ab + k0);
            bv = *(const float4*)(Bb + (size_t)k0 * 128);
        }
        COMPUTE_KSTEPS(buf);
        if (k0 < 512) {
            buf ^= 1;
            STORE_A_TILE(buf, av);
            *(float4*)&Bs[buf][b_r][b_c] = bv;
            __syncthreads();
        }
    }

    const int row0 = blockIdx.y * 128;
    const int c0 = (tx << 2);
    #pragma unroll
    for (int i = 0; i < 8; i++) {
        int r = row0 + ((i < 4) ? (ty << 2) + i : 64 + (ty << 2) + (i - 4));
        *(float4*)(g_qk + (size_t)r * 128 + c0)      = make_float4(acc[i][0], acc[i][1], acc[i][2], acc[i][3]);
        *(float4*)(g_qk + (size_t)r * 128 + c0 + 64) = make_float4(acc[i][4], acc[i][5], acc[i][6], acc[i][7]);
    }
}

// Row softmax, vectorized: fp32 logits in, fp16 probs out
__global__ __launch_bounds__(256) void softmax_rows() {
    const float4* p4 = (const float4*)(g_s + (size_t)blockIdx.x * kHW);
    uint2* ph4 = (uint2*)(g_sh + (size_t)blockIdx.x * kHW);
    const int tid = threadIdx.x;
    __shared__ float red[8], red2[8];

    float4 f[4];
    float m = -1e30f;
    #pragma unroll
    for (int j = 0; j < 4; j++) {
        f[j] = p4[tid + j * 256];
        m = fmaxf(m, fmaxf(fmaxf(f[j].x, f[j].y), fmaxf(f[j].z, f[j].w)));
    }
    #pragma unroll
    for (int o = 16; o > 0; o >>= 1) m = fmaxf(m, __shfl_xor_sync(0xffffffffu, m, o));
    if ((tid & 31) == 0) red[tid >> 5] = m;
    __syncthreads();
    float bm = red[0];
    #pragma unroll
    for (int w = 1; w < 8; w++) bm = fmaxf(bm, red[w]);

    float sum = 0.f;
    #pragma unroll
    for (int j = 0; j < 4; j++) {
        f[j].x = __expf(f[j].x - bm);
        f[j].y = __expf(f[j].y - bm);
        f[j].z = __expf(f[j].z - bm);
        f[j].w = __expf(f[j].w - bm);
        sum += (f[j].x + f[j].y) + (f[j].z + f[j].w);
    }
    #pragma unroll
    for (int o = 16; o > 0; o >>= 1) sum += __shfl_xor_sync(0xffffffffu, sum, o);
    if ((tid & 31) == 0) red2[tid >> 5] = sum;
    __syncthreads();
    float bs = 0.f;
    #pragma unroll
    for (int w = 0; w < 8; w++) bs += red2[w];
    float inv = 1.f / bs;
    #pragma unroll
    for (int j = 0; j < 4; j++) {
        __half2 h0 = __floats2half2_rn(f[j].x * inv, f[j].y * inv);
        __half2 h1 = __floats2half2_rn(f[j].z * inv, f[j].w * inv);
        uint2 u;
        u.x = *reinterpret_cast<uint32_t*>(&h0);
        u.y = *reinterpret_cast<uint32_t*>(&h1);
        ph4[tid + j * 256] = u;
    }
}

// ============ HMMA NT skeleton constants (shared by all HMMA kernels) ======
constexpr int PV_LDA  = 72;                         // halves, padded
constexpr int PV_ABUF = 128 * PV_LDA * 2;           // 18432 B
constexpr int PV_SMEM = 4 * PV_ABUF;                // 73728 B

// ====================== HMMA: PV (E = s @ v), fused epilogue (proven) ======
__global__ void __launch_bounds__(256, 2)
pv_mma(const float* __restrict__ x, const float* __restrict__ gamma,
       float* __restrict__ out) {
    extern __shared__ char smem[];
    const uint32_t sb  = smem_u32(smem);
    const int tid  = threadIdx.x;
    const int lane = tid & 31, wid = tid >> 5;
    const int wm = (wid & 1) * 64, wn = (wid >> 1) * 32;
    const int n0 = blockIdx.x * 128, m0 = blockIdx.y * 128, bz = blockIdx.z;

    const __half* Asrc = g_sh + (size_t)bz * kHW * kHW + (size_t)m0 * kHW;
    const __half* Bsrc = g_vT + (size_t)bz * kC * kHW + (size_t)n0 * kHW;

    const uint32_t sA[2] = {sb, sb + PV_ABUF};
    const uint32_t sB[2] = {sb + 2 * PV_ABUF, sb + 3 * PV_ABUF};

    const int ldrow  = tid >> 3;
    const int ldslot = (tid & 7) * 8;

    float acc[4][4][4];
    #pragma unroll
    for (int i = 0; i < 4; i++)
        #pragma unroll
        for (int j = 0; j < 4; j++)
            #pragma unroll
            for (int r = 0; r < 4; r++) acc[i][j][r] = 0.f;

    const int aRow = wm + (lane & 15);
    const int aCol = (lane >> 4) * 8;
    const int bRow = wn + ((lane >> 4) << 3) + (lane & 7);
    const int bCol = ((lane >> 3) & 1) * 8;

    #pragma unroll
    for (int q = 0; q < 4; q++) {
        int r = q * 32 + ldrow;
        CP16(sA[0] + (r * PV_LDA + ldslot) * 2, Asrc + (size_t)r * kHW + ldslot);
        CP16(sB[0] + (r * PV_LDA + ldslot) * 2, Bsrc + (size_t)r * kHW + ldslot);
    }
    CP_COMMIT();

    for (int i = 0; i < 64; i++) {
        const int buf = i & 1;
        if (i < 63) {
            const int k0 = (i + 1) * 64;
            #pragma unroll
            for (int q = 0; q < 4; q++) {
                int r = q * 32 + ldrow;
                CP16(sA[buf ^ 1] + (r * PV_LDA + ldslot) * 2,
                     Asrc + (size_t)r * kHW + k0 + ldslot);
                CP16(sB[buf ^ 1] + (r * PV_LDA + ldslot) * 2,
                     Bsrc + (size_t)r * kHW + k0 + ldslot);
            }
            CP_COMMIT();
            CP_WAIT(1);
        } else {
            CP_WAIT(0);
        }
        __syncthreads();

        #pragma unroll
        for (int ks = 0; ks < 4; ks++) {
            uint32_t af[4][4], bf[4][2];
            #pragma unroll
            for (int mt = 0; mt < 4; mt++)
                ldmx4(af[mt][0], af[mt][1], af[mt][2], af[mt][3],
                      sA[buf] + ((aRow + mt * 16) * PV_LDA + aCol + ks * 16) * 2);
            #pragma unroll
            for (int np = 0; np < 2; np++)
                ldmx4(bf[np * 2][0], bf[np * 2][1], bf[np * 2 + 1][0], bf[np * 2 + 1][1],
                      sB[buf] + ((bRow + np * 16) * PV_LDA + bCol + ks * 16) * 2);
            #pragma unroll
            for (int mt = 0; mt < 4; mt++)
                #pragma unroll
                for (int nt = 0; nt < 4; nt++)
                    mma16816(acc[mt][nt], af[mt], bf[nt]);
        }
        __syncthreads();
    }

    float* stage = (float*)smem;          // [128][132] as [n][m]
    #pragma unroll
    for (int mt = 0; mt < 4; mt++)
        #pragma unroll
        for (int nt = 0; nt < 4; nt++)
            #pragma unroll
            for (int r = 0; r < 4; r++) {
                int m = wm + mt * 16 + (lane >> 2) + ((r >= 2) ? 8 : 0);
                int n = wn + nt * 8 + (lane & 3) * 2 + (r & 1);
                stage[n * 132 + m] = acc[mt][nt][r];
            }
    __syncthreads();

    const float g = __ldg(gamma);
    const size_t obofs = (size_t)bz * kHW * kC;
    #pragma unroll
    for (int q = 0; q < 16; q++) {
        int idx = tid + q * 256;
        int n   = idx >> 5;
        int m4  = (idx & 31) << 2;
        size_t o = obofs + (size_t)(n0 + n) * kHW + m0 + m4;
        float4 xv = *(const float4*)(x + o);
        const float* sp = stage + n * 132 + m4;
        *(float4*)(out + o) = make_float4(fmaf(g, sp[0], xv.x), fmaf(g, sp[1], xv.y),
                                          fmaf(g, sp[2], xv.z), fmaf(g, sp[3], xv.w));
    }
}

// ============ HMMA: V-proj NT (proven): vT = (x @ W3)^T ====================
__global__ void __launch_bounds__(256, 2) vproj_mma() {
    extern __shared__ char smem[];
    const uint32_t sb  = smem_u32(smem);
    const int tid  = threadIdx.x;
    const int lane = tid & 31, wid = tid >> 5;
    const int wm = (wid & 1) * 64, wn = (wid >> 1) * 32;
    const int n0 = blockIdx.x * 128, m0 = blockIdx.y * 128;

    const __half* Asrc = g_xh + (size_t)m0 * kC;
    const __half* Bsrc = g_w3T + (size_t)n0 * kC;

    const uint32_t sA[2] = {sb, sb + PV_ABUF};
    const uint32_t sB[2] = {sb + 2 * PV_ABUF, sb + 3 * PV_ABUF};

    const int ldrow  = tid >> 3;
    const int ldslot = (tid & 7) * 8;

    float acc[4][4][4];
    #pragma unroll
    for (int i = 0; i < 4; i++)
        #pragma unroll
        for (int j = 0; j < 4; j++)
            #pragma unroll
            for (int r = 0; r < 4; r++) acc[i][j][r] = 0.f;

    const int aRow = wm + (lane & 15);
    const int aCol = (lane >> 4) * 8;
    const int bRow = wn + ((lane >> 4) << 3) + (lane & 7);
    const int bCol = ((lane >> 3) & 1) * 8;

    #pragma unroll
    for (int q = 0; q < 4; q++) {
        int r = q * 32 + ldrow;
        CP16(sA[0] + (r * PV_LDA + ldslot) * 2, Asrc + (size_t)r * kC + ldslot);
        CP16(sB[0] + (r * PV_LDA + ldslot) * 2, Bsrc + (size_t)r * kC + ldslot);
    }
    CP_COMMIT();

    for (int i = 0; i < 8; i++) {
        const int buf = i & 1;
        if (i < 7) {
            const int k0 = (i + 1) * 64;
            #pragma unroll
            for (int q = 0; q < 4; q++) {
                int r = q * 32 + ldrow;
                CP16(sA[buf ^ 1] + (r * PV_LDA + ldslot) * 2,
                     Asrc + (size_t)r * kC + k0 + ldslot);
                CP16(sB[buf ^ 1] + (r * PV_LDA + ldslot) * 2,
                     Bsrc + (size_t)r * kC + k0 + ldslot);
            }
            CP_COMMIT();
            CP_WAIT(1);
        } else {
            CP_WAIT(0);
        }
        __syncthreads();

        #pragma unroll
        for (int ks = 0; ks < 4; ks++) {
            uint32_t af[4][4], bf[4][2];
            #pragma unroll
            for (int mt = 0; mt < 4; mt++)
                ldmx4(af[mt][0], af[mt][1], af[mt][2], af[mt][3],
                      sA[buf] + ((aRow + mt * 16) * PV_LDA + aCol + ks * 16) * 2);
            #pragma unroll
            for (int np = 0; np < 2; np++)
                ldmx4(bf[np * 2][0], bf[np * 2][1], bf[np * 2 + 1][0], bf[np * 2 + 1][1],
                      sB[buf] + ((bRow + np * 16) * PV_LDA + bCol + ks * 16) * 2);
            #pragma unroll
            for (int mt = 0; mt < 4; mt++)
                #pragma unroll
                for (int nt = 0; nt < 4; nt++)
                    mma16816(acc[mt][nt], af[mt], bf[nt]);
        }
        __syncthreads();
    }

    __half* stage = (__half*)smem;        // [128][136]
    constexpr int SLD = 136;
    #pragma unroll
    for (int mt = 0; mt < 4; mt++)
        #pragma unroll
        for (int nt = 0; nt < 4; nt++)
            #pragma unroll
            for (int r = 0; r < 4; r++) {
                int m = wm + mt * 16 + (lane >> 2) + ((r >= 2) ? 8 : 0);
                int n = wn + nt * 8 + (lane & 3) * 2 + (r & 1);
                stage[n * SLD + m] = __float2half_rn(acc[mt][nt][r]);
            }
    __syncthreads();

    const int bz = m0 >> 12;
    const int ml = m0 & 4095;
    #pragma unroll
    for (int q = 0; q < 8; q++) {
        int idx = tid + q * 256;
        int n   = idx >> 4;
        int m8  = (idx & 15) << 3;
        __half* dst = g_vT + ((size_t)bz * kC + n0 + n) * kHW + ml + m8;
        *(uint4*)dst = *(uint4*)(stage + n * SLD + m8);
    }
}

// ========== HMMA: logits via exact 3-term fp16 split (NT skeleton) =========
// s[b,i,j] = q_hi.k_hi + q_lo.k_hi + q_hi.k_lo   (fp32 accum, error ~2^-22)
// A = g_qs [m][hi|lo] ld 128; B = g_ks [n][hi|lo] ld 128.
__global__ void __launch_bounds__(256, 2) logits_split() {
    extern __shared__ char smem[];
    const uint32_t sb  = smem_u32(smem);
    const int tid  = threadIdx.x;
    const int lane = tid & 31, wid = tid >> 5;
    const int wm = (wid & 1) * 64, wn = (wid >> 1) * 32;
    const int n0 = blockIdx.x * 128, m0 = blockIdx.y * 128, bz = blockIdx.z;

    const __half* Asrc = g_qs + ((size_t)bz * kHW + m0) * 128;
    const __half* Bsrc = g_ks + ((size_t)bz * kHW + n0) * 128;

    const uint32_t sA[2] = {sb, sb + PV_ABUF};
    const uint32_t sB[2] = {sb + 2 * PV_ABUF, sb + 3 * PV_ABUF};

    const int ldrow  = tid >> 3;
    const int ldslot = (tid & 7) * 8;

    float acc[4][4][4];
    #pragma unroll
    for (int i = 0; i < 4; i++)
        #pragma unroll
        for (int j = 0; j < 4; j++)
            #pragma unroll
            for (int r = 0; r < 4; r++) acc[i][j][r] = 0.f;

    const int aRow = wm + (lane & 15);
    const int aCol = (lane >> 4) * 8;
    const int bRow = wn + ((lane >> 4) << 3) + (lane & 7);
    const int bCol = ((lane >> 3) & 1) * 8;

    // chunk c: A offset {hi, lo, hi}, B offset {hi, hi, lo}
    const int AOFF[3] = {0, 64, 0};
    const int BOFF[3] = {0, 0, 64};

    #pragma unroll
    for (int q = 0; q < 4; q++) {
        int r = q * 32 + ldrow;
        CP16(sA[0] + (r * PV_LDA + ldslot) * 2, Asrc + (size_t)r * 128 + AOFF[0] + ldslot);
        CP16(sB[0] + (r * PV_LDA + ldslot) * 2, Bsrc + (size_t)r * 128 + BOFF[0] + ldslot);
    }
    CP_COMMIT();

    for (int i = 0; i < 3; i++) {
        const int buf = i & 1;
        if (i < 2) {
            #pragma unroll
            for (int q = 0; q < 4; q++) {
                int r = q * 32 + ldrow;
                CP16(sA[buf ^ 1] + (r * PV_LDA + ldslot) * 2,
                     Asrc + (size_t)r * 128 + AOFF[i + 1] + ldslot);
                CP16(sB[buf ^ 1] + (r * PV_LDA + ldslot) * 2,
                     Bsrc + (size_t)r * 128 + BOFF[i + 1] + ldslot);
            }
            CP_COMMIT();
            CP_WAIT(1);
        } else {
            CP_WAIT(0);
        }
        __syncthreads();

        #pragma unroll
        for (int ks = 0; ks < 4; ks++) {
            uint32_t af[4][4], bf[4][2];
            #pragma unroll
            for (int mt = 0; mt < 4; mt++)
                ldmx4(af[mt][0], af[mt][1], af[mt][2], af[mt][3],
                      sA[buf] + ((aRow + mt * 16) * PV_LDA + aCol + ks * 16) * 2);
            #pragma unroll
            for (int np = 0; np < 2; np++)
                ldmx4(bf[np * 2][0], bf[np * 2][1], bf[np * 2 + 1][0], bf[np * 2 + 1][1],
                      sB[buf] + ((bRow + np * 16) * PV_LDA + bCol + ks * 16) * 2);
            #pragma unroll
            for (int mt = 0; mt < 4; mt++)
                #pragma unroll
                for (int nt = 0; nt < 4; nt++)
                    mma16816(acc[mt][nt], af[mt], bf[nt]);
        }
        __syncthreads();
    }

    // stage [m][n] fp32 -> coalesced row-major logits writes
    float* stage = (float*)smem;          // [128][132]
    #pragma unroll
    for (int mt = 0; mt < 4; mt++)
        #pragma unroll
        for (int nt = 0; nt < 4; nt++)
            #pragma unroll
            for (int r = 0; r < 4; r++) {
                int m = wm + mt * 16 + (lane >> 2) + ((r >= 2) ? 8 : 0);
                int n = wn + nt * 8 + (lane & 3) * 2 + (r & 1);
                stage[m * 132 + n] = acc[mt][nt][r];
            }
    __syncthreads();

    float* Cp = g_s + (size_t)bz * kHW * kHW;
    #pragma unroll
    for (int q = 0; q < 16; q++) {
        int idx = tid + q * 256;
        int m   = idx >> 5;
        int n4  = (idx & 31) << 2;
        *(float4*)(Cp + (size_t)(m0 + m) * kHW + n0 + n4) = *(float4*)(stage + m * 132 + n4);
    }
}

// ---------------------------------------------------------------------------
extern "C" void kernel_launch(void* const* d_in, const int* in_sizes, int n_in,
                              void* d_out, int out_size) {
    const float* x     = (const float*)d_in[0];
    const float* W1    = (const float*)d_in[1];
    const float* W2    = (const float*)d_in[2];
    const float* W3    = (const float*)d_in[3];
    const float* gamma = (const float*)d_in[4];
    float* out = (float*)d_out;

    cudaFuncSetAttribute(pv_mma, cudaFuncAttributeMaxDynamicSharedMemorySize, PV_SMEM);
    cudaFuncSetAttribute(vproj_mma, cudaFuncAttributeMaxDynamicSharedMemorySize, PV_SMEM);
    cudaFuncSetAttribute(logits_split, cudaFuncAttributeMaxDynamicSharedMemorySize, PV_SMEM);

    concat_w<<<256, 256>>>(W1, W2);
    to_half_x<<<8192, 256>>>(x);                          // x fp16 [m][k]
    transpose_w3<<<dim3(16, 16), 256>>>(W3);              // W3^T fp16 [n][k]
    proj_gemm<<<dim3(1, 128), 256>>>(x);                  // q|k fp32 (proven)
    split_qk<<<8192, 256>>>();                            // q,k -> hi/lo fp16
    vproj_mma<<<dim3(4, 128), 256, PV_SMEM>>>();          // vT fp16 (proven)
    logits_split<<<dim3(32, 32, 4), 256, PV_SMEM>>>();    // fp32 logits (HMMA split)
    softmax_rows<<<16384, 256>>>();                       // fp16 probs (vectorized)
    pv_mma<<<dim3(4, 32, 4), 256, PV_SMEM>>>(x, gamma, out);
}